// round 4
// baseline (speedup 1.0000x reference)
#include <cuda_runtime.h>
#include <cuda_bf16.h>
#include <cstdint>

// Problem constants
#define B_SZ 4096
#define N_SZ 8192
#define D_SZ 128
// zn rows pre-scaled by sqrt(INV_TEMP * log2(e)); accumulator is log2-units.
#define PRESCALE 1.69864360f   // sqrt(2 * 1.44269504)
#define LN2 0.69314718056f

// Tiling
#define M_BLK  64            // rows per CTA
#define N_TILE 128           // columns per mainloop iteration
#define LDS    136           // padded smem row stride (bf16 elems)
#define NTILES (N_SZ / N_TILE)

// Scratch (no allocations allowed)
__device__ __nv_bfloat16 g_zn[N_SZ * D_SZ];   // normalized+prescaled embeddings (2 MB)
__device__ float g_rowloss[N_SZ];

// ---------------------------------------------------------------------------
// Kernel 1: row-normalize z = concat(z_i, z_j), prescale, store bf16
// ---------------------------------------------------------------------------
__global__ void norm_kernel(const float* __restrict__ zi, const float* __restrict__ zj) {
    const int r = blockIdx.x;
    const int d = threadIdx.x;                 // 128 threads = D
    const float* src = (r < B_SZ) ? (zi + (size_t)r * D_SZ)
                                  : (zj + (size_t)(r - B_SZ) * D_SZ);
    float v = src[d];
    float sq = v * v;
    #pragma unroll
    for (int off = 16; off > 0; off >>= 1)
        sq += __shfl_xor_sync(0xffffffffu, sq, off);
    __shared__ float ws[4];
    if ((d & 31) == 0) ws[d >> 5] = sq;
    __syncthreads();
    float tot = ws[0] + ws[1] + ws[2] + ws[3];
    float nrm = fmaxf(sqrtf(tot), 1e-8f);
    g_zn[r * D_SZ + d] = __float2bfloat16(v * (PRESCALE / nrm));
}

// ---------------------------------------------------------------------------
// PTX helpers
// ---------------------------------------------------------------------------
__device__ __forceinline__ uint32_t smem_u32(const void* p) {
    return (uint32_t)__cvta_generic_to_shared(p);
}
__device__ __forceinline__ void ldsm_x4(uint32_t& r0, uint32_t& r1, uint32_t& r2, uint32_t& r3,
                                        uint32_t a) {
    asm volatile("ldmatrix.sync.aligned.m8n8.x4.shared.b16 {%0,%1,%2,%3}, [%4];\n"
                 : "=r"(r0), "=r"(r1), "=r"(r2), "=r"(r3) : "r"(a));
}
__device__ __forceinline__ void mma16816(float c[4], const uint32_t a[4],
                                         uint32_t b0, uint32_t b1) {
    asm volatile(
        "mma.sync.aligned.m16n8k16.row.col.f32.bf16.bf16.f32 "
        "{%0,%1,%2,%3}, {%4,%5,%6,%7}, {%8,%9}, {%0,%1,%2,%3};\n"
        : "+f"(c[0]), "+f"(c[1]), "+f"(c[2]), "+f"(c[3])
        : "r"(a[0]), "r"(a[1]), "r"(a[2]), "r"(a[3]), "r"(b0), "r"(b1));
}
__device__ __forceinline__ float ex2f(float x) {
    float y;
    asm("ex2.approx.f32 %0, %1;\n" : "=f"(y) : "f"(x));
    return y;
}
__device__ __forceinline__ void cp16(uint32_t dst, const void* src) {
    asm volatile("cp.async.cg.shared.global [%0], [%1], 16;\n" :: "r"(dst), "l"(src));
}
__device__ __forceinline__ void cp_commit() { asm volatile("cp.async.commit_group;\n"); }

__device__ __forceinline__ void prefetchB(uint32_t bs_u, int ci, int tid) {
    const int c0 = ci * N_TILE;
    #pragma unroll
    for (int i = 0; i < 8; i++) {
        int q = tid + i * 256;                 // 128 rows * 16 chunks
        int row = q >> 4, ch = q & 15;
        cp16(bs_u + (uint32_t)(row * LDS + ch * 8) * 2,
             g_zn + (size_t)(c0 + row) * D_SZ + ch * 8);
    }
}

// ---------------------------------------------------------------------------
// Kernel 2: fused sim-GEMM + exp2-sum + per-row loss
// Block: 256 threads = 8 warps, warp tile 32x32 (wm in {0,1}, wn in {0..3})
// A operand held in registers across the whole column sweep.
// ---------------------------------------------------------------------------
__global__ void __launch_bounds__(256, 1) simloss_kernel() {
    extern __shared__ __align__(16) unsigned char smem_raw[];
    __nv_bfloat16* As  = (__nv_bfloat16*)smem_raw;                    // [64][LDS]
    __nv_bfloat16* Bs0 = As + M_BLK * LDS;                            // [128][LDS] x2
    __nv_bfloat16* Bs1 = Bs0 + N_TILE * LDS;

    const int tid  = threadIdx.x;
    const int lane = tid & 31;
    const int warp = tid >> 5;
    const int wm   = warp >> 2;     // 0..1
    const int wn   = warp & 3;      // 0..3
    const int gid  = lane >> 2;
    const int tig  = lane & 3;
    const int blockRow = blockIdx.x * M_BLK;

    const uint32_t As_u = smem_u32(As);
    const uint32_t Bs_u[2] = { smem_u32(Bs0), smem_u32(Bs1) };

    // Prologue: stage A tile (64x128) + B tile 0, drain, hoist A to registers
    #pragma unroll
    for (int i = 0; i < 4; i++) {
        int q = tid + i * 256;                 // 64 rows * 16 chunks
        int row = q >> 4, ch = q & 15;
        cp16(As_u + (uint32_t)(row * LDS + ch * 8) * 2,
             g_zn + (size_t)(blockRow + row) * D_SZ + ch * 8);
    }
    prefetchB(Bs_u[0], 0, tid);
    cp_commit();
    asm volatile("cp.async.wait_group 0;\n");
    __syncthreads();

    // ldmatrix per-lane address decomposition
    const int arow = (lane & 7) + ((lane >> 3) & 1) * 8;   // A: m0/m1 rows, m2/m3 k-hi
    const int acol = (lane >> 4) * 8;
    const int brow = (lane & 7) + ((lane >> 4) & 1) * 8;   // B: x4 packs two n-tiles
    const int bcol = ((lane >> 3) & 1) * 8;

    // A fragments: invariant across all column tiles -> load once (64 regs)
    uint32_t a[2][8][4];
    #pragma unroll
    for (int mi = 0; mi < 2; mi++)
        #pragma unroll
        for (int kk = 0; kk < 8; kk++)
            ldsm_x4(a[mi][kk][0], a[mi][kk][1], a[mi][kk][2], a[mi][kk][3],
                    As_u + (uint32_t)((wm * 32 + mi * 16 + arow) * LDS + kk * 16 + acol) * 2);

    float sumE[2][2][2] = {};   // [mi][h][e] two accumulators per row for FADD ILP
    float pos[2][2] = {{0.f, 0.f}, {0.f, 0.f}};
    int rown[2][2];
    #pragma unroll
    for (int mi = 0; mi < 2; mi++) {
        rown[mi][0] = blockRow + wm * 32 + mi * 16 + gid;
        rown[mi][1] = rown[mi][0] + 8;
    }
    const int warpRowLo = blockRow + wm * 32;              // 32-row band of this warp

    for (int ci = 0; ci < NTILES; ci++) {
        const int buf = ci & 1;
        if (ci + 1 < NTILES) {
            prefetchB(Bs_u[buf ^ 1], ci + 1, tid);
            cp_commit();
            asm volatile("cp.async.wait_group 1;\n");
        } else {
            asm volatile("cp.async.wait_group 0;\n");
        }
        __syncthreads();

        float c[2][4][4];
        #pragma unroll
        for (int mi = 0; mi < 2; mi++)
            #pragma unroll
            for (int ni = 0; ni < 4; ni++)
                c[mi][ni][0] = c[mi][ni][1] = c[mi][ni][2] = c[mi][ni][3] = 0.f;

        #pragma unroll
        for (int kk = 0; kk < 8; kk++) {
            uint32_t b[2][4];
            #pragma unroll
            for (int p = 0; p < 2; p++)
                ldsm_x4(b[p][0], b[p][1], b[p][2], b[p][3],
                        Bs_u[buf] + (uint32_t)((wn * 32 + p * 16 + brow) * LDS + kk * 16 + bcol) * 2);
            #pragma unroll
            for (int mi = 0; mi < 2; mi++)
                #pragma unroll
                for (int p = 0; p < 2; p++) {
                    mma16816(c[mi][2 * p],     a[mi][kk], b[p][0], b[p][1]);
                    mma16816(c[mi][2 * p + 1], a[mi][kk], b[p][2], b[p][3]);
                }
        }

        // epilogue: accumulator already in log2 units -> bare ex2
        const int c0col = ci * N_TILE + wn * 32;
        const bool special = (c0col == warpRowLo) | (c0col == (warpRowLo ^ B_SZ));
        if (!special) {
            // fast path: no diagonal / no positive in this warp tile
            #pragma unroll
            for (int mi = 0; mi < 2; mi++)
                #pragma unroll
                for (int ni = 0; ni < 4; ni++)
                    #pragma unroll
                    for (int h = 0; h < 2; h++) {
                        sumE[mi][h][0] += ex2f(c[mi][ni][h * 2 + 0]);
                        sumE[mi][h][1] += ex2f(c[mi][ni][h * 2 + 1]);
                    }
        } else {
            #pragma unroll
            for (int mi = 0; mi < 2; mi++)
                #pragma unroll
                for (int ni = 0; ni < 4; ni++) {
                    const int colb = c0col + ni * 8 + tig * 2;
                    #pragma unroll
                    for (int h = 0; h < 2; h++) {
                        const int r = rown[mi][h];
                        #pragma unroll
                        for (int e = 0; e < 2; e++) {
                            const int col = colb + e;
                            float d  = c[mi][ni][h * 2 + e];   // log2-units logit
                            float ex = ex2f(d);
                            sumE[mi][h][e] += (col != r) ? ex : 0.f;
                            if (col == (r ^ B_SZ)) pos[mi][h] = d;
                        }
                    }
                }
        }
        __syncthreads();   // all warps done with buf before it is re-prefetched
    }

    // fold dual accumulators, reduce across quad lanes, then across wn warps
    float sum[2][2];
    #pragma unroll
    for (int mi = 0; mi < 2; mi++)
        #pragma unroll
        for (int h = 0; h < 2; h++) {
            float s = sumE[mi][h][0] + sumE[mi][h][1];
            float p = pos[mi][h];
            s += __shfl_xor_sync(0xffffffffu, s, 1);
            s += __shfl_xor_sync(0xffffffffu, s, 2);
            p += __shfl_xor_sync(0xffffffffu, p, 1);
            p += __shfl_xor_sync(0xffffffffu, p, 2);
            sum[mi][h] = s; pos[mi][h] = p;
        }

    float* redS = (float*)smem_raw;        // [64][4]
    float* redP = redS + 256;              // [64][4]
    if (tig == 0) {
        #pragma unroll
        for (int mi = 0; mi < 2; mi++)
            #pragma unroll
            for (int h = 0; h < 2; h++) {
                const int rl = wm * 32 + mi * 16 + gid + h * 8;
                redS[rl * 4 + wn] = sum[mi][h];
                redP[rl * 4 + wn] = pos[mi][h];
            }
    }
    __syncthreads();
    if (tid < M_BLK) {
        float S = redS[tid * 4] + redS[tid * 4 + 1] + redS[tid * 4 + 2] + redS[tid * 4 + 3];
        float P = redP[tid * 4] + redP[tid * 4 + 1] + redP[tid * 4 + 2] + redP[tid * 4 + 3];
        // loss_r = ln(S) - s_pos ;  s_pos(natural) = P(log2 units) * ln2
        g_rowloss[blockRow + tid] = logf(S) - P * LN2;
    }
}

// ---------------------------------------------------------------------------
// Kernel 3: deterministic final reduction
// ---------------------------------------------------------------------------
__global__ void reduce_kernel(float* __restrict__ out) {
    __shared__ float sh[256];
    const int tid = threadIdx.x;
    float s = 0.f;
    for (int i = tid; i < N_SZ; i += 256) s += g_rowloss[i];
    sh[tid] = s;
    __syncthreads();
    #pragma unroll
    for (int off = 128; off > 0; off >>= 1) {
        if (tid < off) sh[tid] += sh[tid + off];
        __syncthreads();
    }
    if (tid == 0) out[0] = sh[0] / (float)N_SZ;
}

// ---------------------------------------------------------------------------
extern "C" void kernel_launch(void* const* d_in, const int* in_sizes, int n_in,
                              void* d_out, int out_size) {
    const float* zi = (const float*)d_in[0];
    const float* zj = (const float*)d_in[1];
    float* out = (float*)d_out;

    const int SMEM_BYTES = (M_BLK * LDS + 2 * N_TILE * LDS) * 2;   // 87040 B
    cudaFuncSetAttribute(simloss_kernel, cudaFuncAttributeMaxDynamicSharedMemorySize, SMEM_BYTES);

    norm_kernel<<<N_SZ, D_SZ>>>(zi, zj);
    simloss_kernel<<<N_SZ / M_BLK, 256, SMEM_BYTES>>>();
    reduce_kernel<<<1, 256>>>(out);
}

// round 10
// speedup vs baseline: 1.1305x; 1.1305x over previous
#include <cuda_runtime.h>
#include <cuda_bf16.h>
#include <cstdint>

// Problem constants
#define B_SZ 4096
#define N_SZ 8192
#define D_SZ 128
// zn rows pre-scaled by sqrt(INV_TEMP * log2(e)); accumulator is log2-units.
#define PRESCALE 1.69864360f   // sqrt(2 * 1.44269504)
#define LN2 0.69314718056f

// Tiling
#define M_BLK  64            // rows per CTA
#define N_TILE 128           // columns per mainloop iteration
#define LDS    136           // padded smem row stride (bf16 elems)
#define NTILES (N_SZ / N_TILE)

// Scratch (no allocations allowed)
__device__ __nv_bfloat16 g_zn[N_SZ * D_SZ];   // normalized+prescaled embeddings (2 MB)
__device__ float g_rowloss[N_SZ];

// ---------------------------------------------------------------------------
// Kernel 1: row-normalize, warp per row, float4 loads
// ---------------------------------------------------------------------------
__global__ void norm_kernel(const float* __restrict__ zi, const float* __restrict__ zj) {
    const int gw   = (blockIdx.x * blockDim.x + threadIdx.x) >> 5;   // global warp = row
    const int lane = threadIdx.x & 31;
    const float* srcRow = (gw < B_SZ) ? (zi + (size_t)gw * D_SZ)
                                      : (zj + (size_t)(gw - B_SZ) * D_SZ);
    float4 v = ((const float4*)srcRow)[lane];
    float sq = v.x * v.x + v.y * v.y + v.z * v.z + v.w * v.w;
    #pragma unroll
    for (int off = 16; off > 0; off >>= 1)
        sq += __shfl_xor_sync(0xffffffffu, sq, off);
    float nrm = fmaxf(sqrtf(sq), 1e-8f);
    float s = PRESCALE / nrm;
    __nv_bfloat162 lo = __nv_bfloat162(__float2bfloat16(v.x * s), __float2bfloat16(v.y * s));
    __nv_bfloat162 hi = __nv_bfloat162(__float2bfloat16(v.z * s), __float2bfloat16(v.w * s));
    uint2 packed;
    packed.x = *(uint32_t*)&lo;
    packed.y = *(uint32_t*)&hi;
    ((uint2*)(g_zn + (size_t)gw * D_SZ))[lane] = packed;
}

// ---------------------------------------------------------------------------
// PTX helpers
// ---------------------------------------------------------------------------
__device__ __forceinline__ uint32_t smem_u32(const void* p) {
    return (uint32_t)__cvta_generic_to_shared(p);
}
__device__ __forceinline__ void ldsm_x4(uint32_t& r0, uint32_t& r1, uint32_t& r2, uint32_t& r3,
                                        uint32_t a) {
    asm volatile("ldmatrix.sync.aligned.m8n8.x4.shared.b16 {%0,%1,%2,%3}, [%4];\n"
                 : "=r"(r0), "=r"(r1), "=r"(r2), "=r"(r3) : "r"(a));
}
__device__ __forceinline__ void mma16816(float c[4], const uint32_t a[4],
                                         uint32_t b0, uint32_t b1) {
    asm volatile(
        "mma.sync.aligned.m16n8k16.row.col.f32.bf16.bf16.f32 "
        "{%0,%1,%2,%3}, {%4,%5,%6,%7}, {%8,%9}, {%0,%1,%2,%3};\n"
        : "+f"(c[0]), "+f"(c[1]), "+f"(c[2]), "+f"(c[3])
        : "r"(a[0]), "r"(a[1]), "r"(a[2]), "r"(a[3]), "r"(b0), "r"(b1));
}
__device__ __forceinline__ float ex2f(float x) {
    float y;
    asm("ex2.approx.f32 %0, %1;\n" : "=f"(y) : "f"(x));
    return y;
}
__device__ __forceinline__ void cp16(uint32_t dst, const void* src) {
    asm volatile("cp.async.cg.shared.global [%0], [%1], 16;\n" :: "r"(dst), "l"(src));
}
__device__ __forceinline__ void cp_commit() { asm volatile("cp.async.commit_group;\n"); }

__device__ __forceinline__ void prefetchB(uint32_t bs_u, int ci, int tid) {
    const int c0 = ci * N_TILE;
    #pragma unroll
    for (int i = 0; i < 8; i++) {
        int q = tid + i * 256;                 // 128 rows * 16 chunks
        int row = q >> 4, ch = q & 15;
        cp16(bs_u + (uint32_t)(row * LDS + ch * 8) * 2,
             g_zn + (size_t)(c0 + row) * D_SZ + ch * 8);
    }
}

// ---------------------------------------------------------------------------
// Kernel 2: fused sim-GEMM + exp2-sum, epilogue software-pipelined into the
// next tile's kk-loop. 256 threads, warp tile 32x32. A held in registers.
// ---------------------------------------------------------------------------

// Fast-path epilogue chunk for the PREVIOUS tile: 4 exps folded into kk-step.
// pend==0.f makes it a no-op (buffers are zero-initialized -> ex2(0)=1, fma*0).
#define CHUNK_EXP(CP, KK)                                                     \
    {                                                                         \
        const int mi_ = (KK) >> 2, ni_ = (KK) & 3;                            \
        sumE[mi_][0][0] = fmaf(pend, ex2f(CP[mi_][ni_][0]), sumE[mi_][0][0]); \
        sumE[mi_][0][1] = fmaf(pend, ex2f(CP[mi_][ni_][1]), sumE[mi_][0][1]); \
        sumE[mi_][1][0] = fmaf(pend, ex2f(CP[mi_][ni_][2]), sumE[mi_][1][0]); \
        sumE[mi_][1][1] = fmaf(pend, ex2f(CP[mi_][ni_][3]), sumE[mi_][1][1]); \
    }

// Full epilogue with diagonal / positive handling (runs for 2 of 64 tiles).
#define FULL_EPI(CC, C0COL)                                                   \
    {                                                                         \
        _Pragma("unroll")                                                     \
        for (int mi = 0; mi < 2; mi++)                                        \
            _Pragma("unroll")                                                 \
            for (int ni = 0; ni < 4; ni++) {                                  \
                const int colb = (C0COL) + ni * 8 + tig * 2;                  \
                _Pragma("unroll")                                             \
                for (int h = 0; h < 2; h++) {                                 \
                    const int r = rown[mi][h];                                \
                    _Pragma("unroll")                                         \
                    for (int e = 0; e < 2; e++) {                             \
                        const int col = colb + e;                             \
                        float d  = CC[mi][ni][h * 2 + e];                     \
                        float ex = ex2f(d);                                   \
                        sumE[mi][h][e] += (col != r) ? ex : 0.f;              \
                        if (col == (r ^ B_SZ)) pos[mi][h] = d;                \
                    }                                                         \
                }                                                             \
            }                                                                 \
    }

// One tile: prefetch next B, mainloop with interleaved prev-tile exps.
#define TILE_BODY(CCUR, CPREV, CI)                                            \
    {                                                                         \
        const int buf_ = (CI) & 1;                                            \
        if ((CI) + 1 < NTILES) {                                              \
            prefetchB(Bs_u[buf_ ^ 1], (CI) + 1, tid);                         \
            cp_commit();                                                      \
            asm volatile("cp.async.wait_group 1;\n");                         \
        } else {                                                              \
            asm volatile("cp.async.wait_group 0;\n");                         \
        }                                                                     \
        __syncthreads();                                                      \
        const float pend = prev_pending ? 1.f : 0.f;                          \
        _Pragma("unroll")                                                     \
        for (int mi = 0; mi < 2; mi++)                                        \
            _Pragma("unroll")                                                 \
            for (int ni = 0; ni < 4; ni++) {                                  \
                CCUR[mi][ni][0] = 0.f; CCUR[mi][ni][1] = 0.f;                 \
                CCUR[mi][ni][2] = 0.f; CCUR[mi][ni][3] = 0.f;                 \
            }                                                                 \
        _Pragma("unroll")                                                     \
        for (int kk = 0; kk < 8; kk++) {                                      \
            uint32_t b[2][4];                                                 \
            _Pragma("unroll")                                                 \
            for (int p = 0; p < 2; p++)                                       \
                ldsm_x4(b[p][0], b[p][1], b[p][2], b[p][3],                   \
                        Bs_u[buf_] + (uint32_t)((wn * 32 + p * 16 + brow) * LDS \
                                                + kk * 16 + bcol) * 2);       \
            CHUNK_EXP(CPREV, kk);                                             \
            _Pragma("unroll")                                                 \
            for (int mi = 0; mi < 2; mi++)                                    \
                _Pragma("unroll")                                             \
                for (int p = 0; p < 2; p++) {                                 \
                    mma16816(CCUR[mi][2 * p],     a[mi][kk], b[p][0], b[p][1]); \
                    mma16816(CCUR[mi][2 * p + 1], a[mi][kk], b[p][2], b[p][3]); \
                }                                                             \
        }                                                                     \
        const int c0col_ = (CI) * N_TILE + wn * 32;                           \
        if ((c0col_ == warpRowLo) | (c0col_ == (warpRowLo ^ B_SZ))) {         \
            FULL_EPI(CCUR, c0col_);                                           \
            prev_pending = false;                                             \
        } else {                                                              \
            prev_pending = true;                                              \
        }                                                                     \
        __syncthreads();                                                      \
    }

__global__ void __launch_bounds__(256, 1) simloss_kernel() {
    extern __shared__ __align__(16) unsigned char smem_raw[];
    __nv_bfloat16* As  = (__nv_bfloat16*)smem_raw;                    // [64][LDS]
    __nv_bfloat16* Bs0 = As + M_BLK * LDS;                            // [128][LDS] x2
    __nv_bfloat16* Bs1 = Bs0 + N_TILE * LDS;

    const int tid  = threadIdx.x;
    const int lane = tid & 31;
    const int warp = tid >> 5;
    const int wm   = warp >> 2;     // 0..1
    const int wn   = warp & 3;      // 0..3
    const int gid  = lane >> 2;
    const int tig  = lane & 3;
    const int blockRow = blockIdx.x * M_BLK;

    const uint32_t As_u = smem_u32(As);
    const uint32_t Bs_u[2] = { smem_u32(Bs0), smem_u32(Bs1) };

    // Prologue: stage A tile + B tile 0, drain, hoist A to registers
    #pragma unroll
    for (int i = 0; i < 4; i++) {
        int q = tid + i * 256;                 // 64 rows * 16 chunks
        int row = q >> 4, ch = q & 15;
        cp16(As_u + (uint32_t)(row * LDS + ch * 8) * 2,
             g_zn + (size_t)(blockRow + row) * D_SZ + ch * 8);
    }
    prefetchB(Bs_u[0], 0, tid);
    cp_commit();
    asm volatile("cp.async.wait_group 0;\n");
    __syncthreads();

    const int arow = (lane & 7) + ((lane >> 3) & 1) * 8;
    const int acol = (lane >> 4) * 8;
    const int brow = (lane & 7) + ((lane >> 4) & 1) * 8;
    const int bcol = ((lane >> 3) & 1) * 8;

    uint32_t a[2][8][4];
    #pragma unroll
    for (int mi = 0; mi < 2; mi++)
        #pragma unroll
        for (int kk = 0; kk < 8; kk++)
            ldsm_x4(a[mi][kk][0], a[mi][kk][1], a[mi][kk][2], a[mi][kk][3],
                    As_u + (uint32_t)((wm * 32 + mi * 16 + arow) * LDS + kk * 16 + acol) * 2);

    float sumE[2][2][2] = {};
    float pos[2][2] = {{0.f, 0.f}, {0.f, 0.f}};
    int rown[2][2];
    #pragma unroll
    for (int mi = 0; mi < 2; mi++) {
        rown[mi][0] = blockRow + wm * 32 + mi * 16 + gid;
        rown[mi][1] = rown[mi][0] + 8;
    }
    const int warpRowLo = blockRow + wm * 32;

    // Accumulator double buffers (zero-init so pend=0 chunks are NaN-safe)
    float cA[2][4][4] = {};
    float cB[2][4][4] = {};
    bool prev_pending = false;

    for (int ci2 = 0; ci2 < NTILES; ci2 += 2) {
        TILE_BODY(cA, cB, ci2);
        TILE_BODY(cB, cA, ci2 + 1);
    }
    // Drain final pending tile (NTILES-1 is odd -> lives in cB)
    if (prev_pending) {
        #pragma unroll
        for (int mi = 0; mi < 2; mi++)
            #pragma unroll
            for (int ni = 0; ni < 4; ni++) {
                sumE[mi][0][0] += ex2f(cB[mi][ni][0]);
                sumE[mi][0][1] += ex2f(cB[mi][ni][1]);
                sumE[mi][1][0] += ex2f(cB[mi][ni][2]);
                sumE[mi][1][1] += ex2f(cB[mi][ni][3]);
            }
    }

    // fold dual accumulators, reduce across quad lanes, then across wn warps
    float sum[2][2];
    #pragma unroll
    for (int mi = 0; mi < 2; mi++)
        #pragma unroll
        for (int h = 0; h < 2; h++) {
            float s = sumE[mi][h][0] + sumE[mi][h][1];
            float p = pos[mi][h];
            s += __shfl_xor_sync(0xffffffffu, s, 1);
            s += __shfl_xor_sync(0xffffffffu, s, 2);
            p += __shfl_xor_sync(0xffffffffu, p, 1);
            p += __shfl_xor_sync(0xffffffffu, p, 2);
            sum[mi][h] = s; pos[mi][h] = p;
        }

    float* redS = (float*)smem_raw;        // [64][4]
    float* redP = redS + 256;              // [64][4]
    if (tig == 0) {
        #pragma unroll
        for (int mi = 0; mi < 2; mi++)
            #pragma unroll
            for (int h = 0; h < 2; h++) {
                const int rl = wm * 32 + mi * 16 + gid + h * 8;
                redS[rl * 4 + wn] = sum[mi][h];
                redP[rl * 4 + wn] = pos[mi][h];
            }
    }
    __syncthreads();
    if (tid < M_BLK) {
        float S = redS[tid * 4] + redS[tid * 4 + 1] + redS[tid * 4 + 2] + redS[tid * 4 + 3];
        float P = redP[tid * 4] + redP[tid * 4 + 1] + redP[tid * 4 + 2] + redP[tid * 4 + 3];
        g_rowloss[blockRow + tid] = logf(S) - P * LN2;
    }
}

// ---------------------------------------------------------------------------
// Kernel 3: deterministic final reduction (1024 threads)
// ---------------------------------------------------------------------------
__global__ void reduce_kernel(float* __restrict__ out) {
    __shared__ float sh[1024];
    const int tid = threadIdx.x;
    float s = 0.f;
    #pragma unroll
    for (int i = 0; i < N_SZ / 1024; i++) s += g_rowloss[tid + i * 1024];
    sh[tid] = s;
    __syncthreads();
    #pragma unroll
    for (int off = 512; off > 0; off >>= 1) {
        if (tid < off) sh[tid] += sh[tid + off];
        __syncthreads();
    }
    if (tid == 0) out[0] = sh[0] / (float)N_SZ;
}

// ---------------------------------------------------------------------------
extern "C" void kernel_launch(void* const* d_in, const int* in_sizes, int n_in,
                              void* d_out, int out_size) {
    const float* zi = (const float*)d_in[0];
    const float* zj = (const float*)d_in[1];
    float* out = (float*)d_out;

    const int SMEM_BYTES = (M_BLK * LDS + 2 * N_TILE * LDS) * 2;   // 87040 B
    cudaFuncSetAttribute(simloss_kernel, cudaFuncAttributeMaxDynamicSharedMemorySize, SMEM_BYTES);

    norm_kernel<<<N_SZ / 8, 256>>>(zi, zj);
    simloss_kernel<<<N_SZ / M_BLK, 256, SMEM_BYTES>>>();
    reduce_kernel<<<1, 1024>>>(out);
}